// round 10
// baseline (speedup 1.0000x reference)
#include <cuda_runtime.h>
#include <cuda_fp16.h>
#include <math.h>

#define B_  512
#define R_  1152
#define C_  8
#define J_  10
#define O_  16
#define JO_ 160

// Scratch (device globals: no allocations allowed in kernel_launch)
// u_hat stored fp16, packed across batch pairs: g_U16[p, r, jo] = (u[2p], u[2p+1])
__device__ __half2 g_U16[(size_t)(B_ / 2) * R_ * JO_];   // 188 MB
__device__ float   g_S[3][B_ * JO_];                     // s accumulators
__device__ float   g_V0[B_ * JO_];                       // v0
__device__ float   g_VSUM[B_ * JO_];                     // v0 + v1

__device__ __forceinline__ __half2 h2exp2_(__half2 x) {
    unsigned r, xi = *reinterpret_cast<unsigned*>(&x);
    asm("ex2.approx.f16x2 %0, %1;" : "=r"(r) : "r"(xi));
    return *reinterpret_cast<__half2*>(&r);
}

// ---------------------------------------------------------------------------
__global__ void k_zero() {
    int i = blockIdx.x * blockDim.x + threadIdx.x;
    if (i < 3 * B_ * JO_) ((float*)g_S)[i] = 0.0f;
}

// ---------------------------------------------------------------------------
// u_hat[b,r,jo] = sum_c W[r,jo,c] * x[b,r,c]; fused sum_r u_hat -> g_S[0].
// Each warp owns (8 batches = 4 pairs, 8-r slice). W[r] in 40 regs, reused
// across 8 batches; compute fp32, store packed half2.
// v5: back to 8-r slices (R8 shape); half2 sacc (fewer regs); S0 reduced
// block-first in smem (all 8 warps share b0 since 144%8==0), cutting global
// atomic lane-ops 8x and per-address contention 144 -> 18.
__global__ void __launch_bounds__(256, 3) k_uhat(const float* __restrict__ x,
                                                 const float* __restrict__ W) {
    __shared__ float s_red[8 * JO_];
    const int tid  = threadIdx.x;
    const int lane = tid & 31;
    const int unit = blockIdx.x * 8 + (tid >> 5);
    const int bg   = unit / 144;           // 64 groups of 8 b (uniform per block)
    const int sl   = unit - bg * 144;      // 144 slices of 8 r
    const int b0   = bg * 8;
    const int r0   = sl * 8;

    for (int i = tid; i < 8 * JO_; i += 256) s_red[i] = 0.f;
    __syncthreads();

    __half2 sacc2[4][5];                   // per b-pair, per k
    #pragma unroll
    for (int pp = 0; pp < 4; pp++)
        #pragma unroll
        for (int k = 0; k < 5; k++) sacc2[pp][k] = __floats2half2_rn(0.f, 0.f);

    #pragma unroll
    for (int rq = 0; rq < 2; rq++) {
        const int rbase = r0 + rq * 4;

        // x chunk: per b, 4 r x 8 c = 32 floats, one coalesced load each
        float xq[8];
        #pragma unroll
        for (int bb = 0; bb < 8; bb++)
            xq[bb] = x[(size_t)(b0 + bb) * (R_ * C_) + (size_t)rbase * C_ + lane];

        #pragma unroll
        for (int rr = 0; rr < 4; rr++) {
            const int r = rbase + rr;

            // W[r] -> registers: lane l holds W[r, l+32k, 0..8) as 2 float4
            float4 wa[5], wb[5];
            const float4* Wp =
                (const float4*)(W + (size_t)r * 1280 + (size_t)lane * 8);
            #pragma unroll
            for (int k = 0; k < 5; k++) {
                wa[k] = Wp[k * 64];
                wb[k] = Wp[k * 64 + 1];
            }

            float uhold[5];
            #pragma unroll
            for (int bb = 0; bb < 8; bb++) {
                float xc[8];
                #pragma unroll
                for (int c = 0; c < 8; c++)
                    xc[c] = __shfl_sync(0xffffffffu, xq[bb], rr * 8 + c);

                float u[5];
                #pragma unroll
                for (int k = 0; k < 5; k++) {
                    float t = wa[k].x * xc[0];
                    t = fmaf(wa[k].y, xc[1], t);
                    t = fmaf(wa[k].z, xc[2], t);
                    t = fmaf(wa[k].w, xc[3], t);
                    t = fmaf(wb[k].x, xc[4], t);
                    t = fmaf(wb[k].y, xc[5], t);
                    t = fmaf(wb[k].z, xc[6], t);
                    t = fmaf(wb[k].w, xc[7], t);
                    u[k] = t;
                }

                if (bb & 1) {
                    const int pp = bb >> 1;
                    __half2* up = g_U16 +
                        ((size_t)((b0 >> 1) + pp) * R_ + r) * JO_ + lane;
                    #pragma unroll
                    for (int k = 0; k < 5; k++) {
                        __half2 h = __floats2half2_rn(uhold[k], u[k]);
                        up[32 * k] = h;
                        sacc2[pp][k] = __hadd2(sacc2[pp][k], h);
                    }
                } else {
                    #pragma unroll
                    for (int k = 0; k < 5; k++) uhold[k] = u[k];
                }
            }
        }
    }

    // block-level reduction: warps -> smem (spread-address ATOMS, cheap)
    #pragma unroll
    for (int pp = 0; pp < 4; pp++)
        #pragma unroll
        for (int k = 0; k < 5; k++) {
            float2 s = __half22float2(sacc2[pp][k]);
            int jo = lane + 32 * k;
            atomicAdd(&s_red[(2 * pp)     * JO_ + jo], s.x);
            atomicAdd(&s_red[(2 * pp + 1) * JO_ + jo], s.y);
        }
    __syncthreads();

    // one global atomic pass per block (8x fewer ops, 18-way contention)
    for (int i = tid; i < 8 * JO_; i += 256)
        atomicAdd(&g_S[0][(size_t)b0 * JO_ + i], s_red[i]);
}

// ---------------------------------------------------------------------------
// One routing iteration on a BATCH PAIR per warp: logits for b0 and b1 ride
// in the .x/.y halves of every half2 through the butterfly AND the softmax
// tail (HMAX2 tree, ex2.approx.f16x2, half2 z-tree, h2rcp). c*u accumulated
// with HFMA2 in half2, flushed to fp32 every 3 r (bounds fp16 accum noise).
// Lane l holds jo = l + 32k: lanes 0-15 j=2k, lanes 16-31 j=2k+1.
// v5: block-level smem reduction before global atomics (8 warps per block
// share the same pair p since 64%8==0): 8x fewer global atomic ops.
__global__ void __launch_bounds__(256, 7) k_route(int vsel, int ssel) {
    __shared__ float s_red[2 * JO_];
    const int tid  = threadIdx.x;
    const int lane = tid & 31;
    const int unit = blockIdx.x * 8 + (tid >> 5);
    const int p    = unit >> 6;            // uniform per block
    const int sl   = unit & 63;            // 64 slices of 18 r
    const int b0   = 2 * p, b1 = b0 + 1;

    for (int i = tid; i < 2 * JO_; i += 256) s_red[i] = 0.f;
    __syncthreads();

    const float* __restrict__ V = vsel ? g_VSUM : g_V0;
    const float LOG2E = 1.4426950408889634f;

    __half2 v2[5];
    float sacc0[5] = {0.f, 0.f, 0.f, 0.f, 0.f};
    float sacc1[5] = {0.f, 0.f, 0.f, 0.f, 0.f};
    #pragma unroll
    for (int k = 0; k < 5; k++) {
        int jo = lane + 32 * k;
        v2[k] = __floats2half2_rn(V[b0 * JO_ + jo] * LOG2E,
                                  V[b1 * JO_ + jo] * LOG2E);
    }

    const __half2* __restrict__ up =
        g_U16 + ((size_t)p * R_ + (size_t)sl * 18) * JO_ + lane;

    for (int rq = 0; rq < 6; rq++) {
        __half2 hacc[5];
        #pragma unroll
        for (int k = 0; k < 5; k++) hacc[k] = __floats2half2_rn(0.f, 0.f);

        #pragma unroll
        for (int rr = 0; rr < 3; rr++) {
            __half2 u2[5], ap2[5];
            #pragma unroll
            for (int k = 0; k < 5; k++) u2[k] = up[32 * k];
            up += JO_;

            #pragma unroll
            for (int k = 0; k < 5; k++) ap2[k] = __hmul2(u2[k], v2[k]);

            // reduce over o (16 lanes per j-group), both batches per op
            #pragma unroll
            for (int d = 1; d < 16; d <<= 1) {
                #pragma unroll
                for (int k = 0; k < 5; k++)
                    ap2[k] = __hadd2(ap2[k],
                                     __shfl_xor_sync(0xffffffffu, ap2[k], d));
            }

            // max over all 10 j (both halves independently)
            __half2 m2 = __hmax2(ap2[0], ap2[1]);
            m2 = __hmax2(m2, ap2[2]);
            m2 = __hmax2(m2, ap2[3]);
            m2 = __hmax2(m2, ap2[4]);
            m2 = __hmax2(m2, __shfl_xor_sync(0xffffffffu, m2, 16));

            // e = exp2(a - m); z-tree; c = e / z; hacc += c * u
            #pragma unroll
            for (int k = 0; k < 5; k++) ap2[k] = h2exp2_(__hsub2(ap2[k], m2));
            __half2 z2 = __hadd2(ap2[0], ap2[1]);
            z2 = __hadd2(z2, ap2[2]);
            z2 = __hadd2(z2, ap2[3]);
            z2 = __hadd2(z2, ap2[4]);
            z2 = __hadd2(z2, __shfl_xor_sync(0xffffffffu, z2, 16));
            __half2 rz2 = h2rcp(z2);

            #pragma unroll
            for (int k = 0; k < 5; k++)
                hacc[k] = __hfma2(__hmul2(ap2[k], rz2), u2[k], hacc[k]);
        }

        // flush fp16 partials to fp32
        #pragma unroll
        for (int k = 0; k < 5; k++) {
            float2 t = __half22float2(hacc[k]);
            sacc0[k] += t.x;
            sacc1[k] += t.y;
        }
    }

    // block-level reduction: warps -> smem
    #pragma unroll
    for (int k = 0; k < 5; k++) {
        int jo = lane + 32 * k;
        atomicAdd(&s_red[jo],       sacc0[k]);
        atomicAdd(&s_red[JO_ + jo], sacc1[k]);
    }
    __syncthreads();

    float* __restrict__ Sout = g_S[ssel];
    for (int i = tid; i < 2 * JO_; i += 256)
        atomicAdd(&Sout[(size_t)b0 * JO_ + i], s_red[i]);
}

// ---------------------------------------------------------------------------
// v = squash(S * scale). mode 0: write g_V0. mode 1: g_VSUM = v + g_V0.
// mode 2: write dout (final output, [B,J,O,1] contiguous).
__global__ void k_squash(int ssel, float scale, int mode,
                         float* __restrict__ dout) {
    int i = blockIdx.x * blockDim.x + threadIdx.x;   // over B*J = 5120
    if (i >= B_ * J_) return;
    const float* s = g_S[ssel] + (size_t)i * O_;

    float sv[O_];
    float sq = 0.f;
    #pragma unroll
    for (int o = 0; o < O_; o++) {
        float t = s[o] * scale;
        sv[o] = t;
        sq += t * t;
    }
    float f = (sq / (1.0f + sq)) * rsqrtf(sq + 1e-8f);

    #pragma unroll
    for (int o = 0; o < O_; o++) {
        float vv = sv[o] * f;
        if (mode == 0)      g_V0[(size_t)i * O_ + o]   = vv;
        else if (mode == 1) g_VSUM[(size_t)i * O_ + o] = vv + g_V0[(size_t)i * O_ + o];
        else                dout[(size_t)i * O_ + o]   = vv;
    }
}

// ---------------------------------------------------------------------------
extern "C" void kernel_launch(void* const* d_in, const int* in_sizes, int n_in,
                              void* d_out, int out_size) {
    const float* x = (const float*)d_in[0];   // [512,1152,8]
    const float* W = (const float*)d_in[1];   // [1152,10,16,8]
    float* out = (float*)d_out;               // [512,10,16,1]
    (void)in_sizes; (void)n_in; (void)out_size;

    k_zero<<<240, 1024>>>();                          // zero S0,S1,S2
    k_uhat<<<1152, 256>>>(x, W);                      // u_hat(fp16) + sum_r -> S0
    k_squash<<<20, 256>>>(0, 1.0f / (float)J_, 0, nullptr);  // v0
    k_route<<<2048, 256>>>(0, 1);                     // iter 1 -> S1 (logits u.v0)
    k_squash<<<20, 256>>>(1, 1.0f, 1, nullptr);       // v1, VSUM = v0+v1
    k_route<<<2048, 256>>>(1, 2);                     // iter 2 -> S2 (logits u.(v0+v1))
    k_squash<<<20, 256>>>(2, 1.0f, 2, out);           // v2 -> output
}

// round 11
// speedup vs baseline: 1.0895x; 1.0895x over previous
#include <cuda_runtime.h>
#include <cuda_fp16.h>
#include <math.h>

#define B_  512
#define R_  1152
#define C_  8
#define J_  10
#define O_  16
#define JO_ 160

// Scratch (device globals: no allocations allowed in kernel_launch)
// u_hat stored fp16, packed across batch pairs: g_U16[p, r, jo] = (u[2p], u[2p+1])
__device__ __half2 g_U16[(size_t)(B_ / 2) * R_ * JO_];   // 188 MB
__device__ float   g_S[3][B_ * JO_];                     // s accumulators
__device__ float   g_V0[B_ * JO_];                       // v0
__device__ float   g_VSUM[B_ * JO_];                     // v0 + v1

__device__ __forceinline__ __half2 h2exp2_(__half2 x) {
    unsigned r, xi = *reinterpret_cast<unsigned*>(&x);
    asm("ex2.approx.f16x2 %0, %1;" : "=r"(r) : "r"(xi));
    return *reinterpret_cast<__half2*>(&r);
}

// ---------------------------------------------------------------------------
__global__ void k_zero() {
    int i = blockIdx.x * blockDim.x + threadIdx.x;
    if (i < 3 * B_ * JO_) ((float*)g_S)[i] = 0.0f;
}

// ---------------------------------------------------------------------------
// u_hat[b,r,jo] = sum_c W[r,jo,c] * x[b,r,c]; fused sum_r u_hat -> g_S[0].
// Each warp owns (8 batches = 4 pairs, 8-r slice). W[r] in 40 regs, reused
// across 8 batches; compute fp32, store packed half2.
// v6: R8 shape — plain __launch_bounds__(256), NO min-blocks clause: the
// (256,3) cap forced an 85-reg ceiling on a ~96-reg body -> local-memory
// spills in the hot loop (R9/R10 regression). Keep R10's smem block
// reduction for S0 (8 warps share b0; 8x fewer global atomics).
__global__ void __launch_bounds__(256) k_uhat(const float* __restrict__ x,
                                              const float* __restrict__ W) {
    __shared__ float s_red[8 * JO_];
    const int tid  = threadIdx.x;
    const int lane = tid & 31;
    const int unit = blockIdx.x * 8 + (tid >> 5);
    const int bg   = unit / 144;           // 64 groups of 8 b (uniform per block)
    const int sl   = unit - bg * 144;      // 144 slices of 8 r
    const int b0   = bg * 8;
    const int r0   = sl * 8;

    for (int i = tid; i < 8 * JO_; i += 256) s_red[i] = 0.f;
    __syncthreads();

    __half2 sacc2[4][5];                   // per b-pair, per k
    #pragma unroll
    for (int pp = 0; pp < 4; pp++)
        #pragma unroll
        for (int k = 0; k < 5; k++) sacc2[pp][k] = __floats2half2_rn(0.f, 0.f);

    #pragma unroll
    for (int rq = 0; rq < 2; rq++) {
        const int rbase = r0 + rq * 4;

        // x chunk: per b, 4 r x 8 c = 32 floats, one coalesced load each
        float xq[8];
        #pragma unroll
        for (int bb = 0; bb < 8; bb++)
            xq[bb] = x[(size_t)(b0 + bb) * (R_ * C_) + (size_t)rbase * C_ + lane];

        #pragma unroll
        for (int rr = 0; rr < 4; rr++) {
            const int r = rbase + rr;

            // W[r] -> registers: lane l holds W[r, l+32k, 0..8) as 2 float4
            float4 wa[5], wb[5];
            const float4* Wp =
                (const float4*)(W + (size_t)r * 1280 + (size_t)lane * 8);
            #pragma unroll
            for (int k = 0; k < 5; k++) {
                wa[k] = Wp[k * 64];
                wb[k] = Wp[k * 64 + 1];
            }

            float uhold[5];
            #pragma unroll
            for (int bb = 0; bb < 8; bb++) {
                float xc[8];
                #pragma unroll
                for (int c = 0; c < 8; c++)
                    xc[c] = __shfl_sync(0xffffffffu, xq[bb], rr * 8 + c);

                float u[5];
                #pragma unroll
                for (int k = 0; k < 5; k++) {
                    float t = wa[k].x * xc[0];
                    t = fmaf(wa[k].y, xc[1], t);
                    t = fmaf(wa[k].z, xc[2], t);
                    t = fmaf(wa[k].w, xc[3], t);
                    t = fmaf(wb[k].x, xc[4], t);
                    t = fmaf(wb[k].y, xc[5], t);
                    t = fmaf(wb[k].z, xc[6], t);
                    t = fmaf(wb[k].w, xc[7], t);
                    u[k] = t;
                }

                if (bb & 1) {
                    const int pp = bb >> 1;
                    __half2* up = g_U16 +
                        ((size_t)((b0 >> 1) + pp) * R_ + r) * JO_ + lane;
                    #pragma unroll
                    for (int k = 0; k < 5; k++) {
                        __half2 h = __floats2half2_rn(uhold[k], u[k]);
                        up[32 * k] = h;
                        sacc2[pp][k] = __hadd2(sacc2[pp][k], h);
                    }
                } else {
                    #pragma unroll
                    for (int k = 0; k < 5; k++) uhold[k] = u[k];
                }
            }
        }
    }

    // block-level reduction: warps -> smem (spread-address ATOMS, cheap)
    #pragma unroll
    for (int pp = 0; pp < 4; pp++)
        #pragma unroll
        for (int k = 0; k < 5; k++) {
            float2 s = __half22float2(sacc2[pp][k]);
            int jo = lane + 32 * k;
            atomicAdd(&s_red[(2 * pp)     * JO_ + jo], s.x);
            atomicAdd(&s_red[(2 * pp + 1) * JO_ + jo], s.y);
        }
    __syncthreads();

    // one global atomic pass per block (8x fewer ops, 18-way contention)
    for (int i = tid; i < 8 * JO_; i += 256)
        atomicAdd(&g_S[0][(size_t)b0 * JO_ + i], s_red[i]);
}

// ---------------------------------------------------------------------------
// One routing iteration on a BATCH PAIR per warp: logits for b0 and b1 ride
// in the .x/.y halves of every half2 through the butterfly AND the softmax
// tail (HMAX2 tree, ex2.approx.f16x2, half2 z-tree, h2rcp). c*u accumulated
// with HFMA2 in half2, flushed to fp32 every 3 r (bounds fp16 accum noise).
// Lane l holds jo = l + 32k: lanes 0-15 j=2k, lanes 16-31 j=2k+1.
// Block-level smem reduction before global atomics (8 warps per block share
// the same pair p since 64%8==0): 8x fewer global atomic ops.
// (unchanged from R10: 55.6us measured best)
__global__ void __launch_bounds__(256, 7) k_route(int vsel, int ssel) {
    __shared__ float s_red[2 * JO_];
    const int tid  = threadIdx.x;
    const int lane = tid & 31;
    const int unit = blockIdx.x * 8 + (tid >> 5);
    const int p    = unit >> 6;            // uniform per block
    const int sl   = unit & 63;            // 64 slices of 18 r
    const int b0   = 2 * p, b1 = b0 + 1;

    for (int i = tid; i < 2 * JO_; i += 256) s_red[i] = 0.f;
    __syncthreads();

    const float* __restrict__ V = vsel ? g_VSUM : g_V0;
    const float LOG2E = 1.4426950408889634f;

    __half2 v2[5];
    float sacc0[5] = {0.f, 0.f, 0.f, 0.f, 0.f};
    float sacc1[5] = {0.f, 0.f, 0.f, 0.f, 0.f};
    #pragma unroll
    for (int k = 0; k < 5; k++) {
        int jo = lane + 32 * k;
        v2[k] = __floats2half2_rn(V[b0 * JO_ + jo] * LOG2E,
                                  V[b1 * JO_ + jo] * LOG2E);
    }

    const __half2* __restrict__ up =
        g_U16 + ((size_t)p * R_ + (size_t)sl * 18) * JO_ + lane;

    for (int rq = 0; rq < 6; rq++) {
        __half2 hacc[5];
        #pragma unroll
        for (int k = 0; k < 5; k++) hacc[k] = __floats2half2_rn(0.f, 0.f);

        #pragma unroll
        for (int rr = 0; rr < 3; rr++) {
            __half2 u2[5], ap2[5];
            #pragma unroll
            for (int k = 0; k < 5; k++) u2[k] = up[32 * k];
            up += JO_;

            #pragma unroll
            for (int k = 0; k < 5; k++) ap2[k] = __hmul2(u2[k], v2[k]);

            // reduce over o (16 lanes per j-group), both batches per op
            #pragma unroll
            for (int d = 1; d < 16; d <<= 1) {
                #pragma unroll
                for (int k = 0; k < 5; k++)
                    ap2[k] = __hadd2(ap2[k],
                                     __shfl_xor_sync(0xffffffffu, ap2[k], d));
            }

            // max over all 10 j (both halves independently)
            __half2 m2 = __hmax2(ap2[0], ap2[1]);
            m2 = __hmax2(m2, ap2[2]);
            m2 = __hmax2(m2, ap2[3]);
            m2 = __hmax2(m2, ap2[4]);
            m2 = __hmax2(m2, __shfl_xor_sync(0xffffffffu, m2, 16));

            // e = exp2(a - m); z-tree; c = e / z; hacc += c * u
            #pragma unroll
            for (int k = 0; k < 5; k++) ap2[k] = h2exp2_(__hsub2(ap2[k], m2));
            __half2 z2 = __hadd2(ap2[0], ap2[1]);
            z2 = __hadd2(z2, ap2[2]);
            z2 = __hadd2(z2, ap2[3]);
            z2 = __hadd2(z2, ap2[4]);
            z2 = __hadd2(z2, __shfl_xor_sync(0xffffffffu, z2, 16));
            __half2 rz2 = h2rcp(z2);

            #pragma unroll
            for (int k = 0; k < 5; k++)
                hacc[k] = __hfma2(__hmul2(ap2[k], rz2), u2[k], hacc[k]);
        }

        // flush fp16 partials to fp32
        #pragma unroll
        for (int k = 0; k < 5; k++) {
            float2 t = __half22float2(hacc[k]);
            sacc0[k] += t.x;
            sacc1[k] += t.y;
        }
    }

    // block-level reduction: warps -> smem
    #pragma unroll
    for (int k = 0; k < 5; k++) {
        int jo = lane + 32 * k;
        atomicAdd(&s_red[jo],       sacc0[k]);
        atomicAdd(&s_red[JO_ + jo], sacc1[k]);
    }
    __syncthreads();

    float* __restrict__ Sout = g_S[ssel];
    for (int i = tid; i < 2 * JO_; i += 256)
        atomicAdd(&Sout[(size_t)b0 * JO_ + i], s_red[i]);
}

// ---------------------------------------------------------------------------
// v = squash(S * scale). mode 0: write g_V0. mode 1: g_VSUM = v + g_V0.
// mode 2: write dout (final output, [B,J,O,1] contiguous).
__global__ void k_squash(int ssel, float scale, int mode,
                         float* __restrict__ dout) {
    int i = blockIdx.x * blockDim.x + threadIdx.x;   // over B*J = 5120
    if (i >= B_ * J_) return;
    const float* s = g_S[ssel] + (size_t)i * O_;

    float sv[O_];
    float sq = 0.f;
    #pragma unroll
    for (int o = 0; o < O_; o++) {
        float t = s[o] * scale;
        sv[o] = t;
        sq += t * t;
    }
    float f = (sq / (1.0f + sq)) * rsqrtf(sq + 1e-8f);

    #pragma unroll
    for (int o = 0; o < O_; o++) {
        float vv = sv[o] * f;
        if (mode == 0)      g_V0[(size_t)i * O_ + o]   = vv;
        else if (mode == 1) g_VSUM[(size_t)i * O_ + o] = vv + g_V0[(size_t)i * O_ + o];
        else                dout[(size_t)i * O_ + o]   = vv;
    }
}

// ---------------------------------------------------------------------------
extern "C" void kernel_launch(void* const* d_in, const int* in_sizes, int n_in,
                              void* d_out, int out_size) {
    const float* x = (const float*)d_in[0];   // [512,1152,8]
    const float* W = (const float*)d_in[1];   // [1152,10,16,8]
    float* out = (float*)d_out;               // [512,10,16,1]
    (void)in_sizes; (void)n_in; (void)out_size;

    k_zero<<<240, 1024>>>();                          // zero S0,S1,S2
    k_uhat<<<1152, 256>>>(x, W);                      // u_hat(fp16) + sum_r -> S0
    k_squash<<<20, 256>>>(0, 1.0f / (float)J_, 0, nullptr);  // v0
    k_route<<<2048, 256>>>(0, 1);                     // iter 1 -> S1 (logits u.v0)
    k_squash<<<20, 256>>>(1, 1.0f, 1, nullptr);       // v1, VSUM = v0+v1
    k_route<<<2048, 256>>>(1, 2);                     // iter 2 -> S2 (logits u.(v0+v1))
    k_squash<<<20, 256>>>(2, 1.0f, 2, out);           // v2 -> output
}

// round 12
// speedup vs baseline: 1.2450x; 1.1427x over previous
#include <cuda_runtime.h>
#include <cuda_fp16.h>
#include <math.h>

#define B_  512
#define R_  1152
#define C_  8
#define J_  10
#define O_  16
#define JO_ 160

// Scratch (device globals: no allocations allowed in kernel_launch)
// u_hat stored fp16, packed across batch pairs: g_U16[p, r, jo] = (u[2p], u[2p+1])
__device__ __half2 g_U16[(size_t)(B_ / 2) * R_ * JO_];   // 188 MB
__device__ float   g_S[3][B_ * JO_];                     // s accumulators
__device__ float   g_V0[B_ * JO_];                       // v0
__device__ float   g_VSUM[B_ * JO_];                     // v0 + v1

__device__ __forceinline__ __half2 h2exp2_(__half2 x) {
    unsigned r, xi = *reinterpret_cast<unsigned*>(&x);
    asm("ex2.approx.f16x2 %0, %1;" : "=r"(r) : "r"(xi));
    return *reinterpret_cast<__half2*>(&r);
}

// ---------------------------------------------------------------------------
__global__ void k_zero() {
    int i = blockIdx.x * blockDim.x + threadIdx.x;
    if (i < 3 * B_ * JO_) ((float*)g_S)[i] = 0.0f;
}

// ---------------------------------------------------------------------------
// u_hat[b,r,jo] = sum_c W[r,jo,c] * x[b,r,c]; fused sum_r u_hat -> g_S[0].
// v7: block = 64 batches x 8 r (was 8 b x 64 r). All 8 warps share the SAME
// 8 W rows -> staged once into 40KB smem (swizzled so wa/wb reads are
// conflict-free LDS.128 at 29cyc instead of LDG from L2 at ~240cyc — the
// long-scoreboard stall that held this kernel at ~100us). W register cache
// and fp32 math unchanged. W L2 traffic drops 8x (377 -> 47 MB). S0 via
// spread-address global atomics (R8-proven; s_red doesn't fit beside W tile).
__global__ void __launch_bounds__(256) k_uhat(const float* __restrict__ x,
                                              const float* __restrict__ W) {
    __shared__ float4 s_w[8 * 320];        // 8 r x 320 float4 = 40KB, swizzled
    const int tid  = threadIdx.x;
    const int lane = tid & 31;
    const int warp = tid >> 5;
    const int sl   = blockIdx.x % 144;     // 144 slices of 8 r
    const int bg   = blockIdx.x / 144;     // 8 groups of 64 b
    const int r0   = sl * 8;
    const int b0   = bg * 64 + warp * 8;   // this warp's 8 batches

    // cooperative W stage: global float4 f of row r -> slot (k*2+ch)*32 + l
    // where jo = f>>1, ch = f&1, k = jo>>5, l = jo&31. Makes the per-warp
    // read  wa[k] = row[(2k)*32 + lane], wb[k] = row[(2k+1)*32 + lane]
    // a conflict-free LDS.128 (32 lanes x 16B contiguous).
    {
        const float4* Wg = (const float4*)(W + (size_t)r0 * 1280);
        for (int i = tid; i < 8 * 320; i += 256) {
            int r  = i >> 8;               // i / 320 below; compute exactly:
            r = i / 320;
            int f  = i - r * 320;
            int jo = f >> 1, ch = f & 1;
            int k  = jo >> 5, l = jo & 31;
            s_w[r * 320 + (k * 2 + ch) * 32 + l] = Wg[r * 320 + f];
        }
    }
    __syncthreads();

    __half2 sacc2[4][5];                   // per b-pair, per k
    #pragma unroll
    for (int pp = 0; pp < 4; pp++)
        #pragma unroll
        for (int k = 0; k < 5; k++) sacc2[pp][k] = __floats2half2_rn(0.f, 0.f);

    #pragma unroll
    for (int rq = 0; rq < 2; rq++) {
        const int rbase = r0 + rq * 4;

        // x chunk: per b, 4 r x 8 c = 32 floats, one coalesced load each
        float xq[8];
        #pragma unroll
        for (int bb = 0; bb < 8; bb++)
            xq[bb] = x[(size_t)(b0 + bb) * (R_ * C_) + (size_t)rbase * C_ + lane];

        #pragma unroll
        for (int rr = 0; rr < 4; rr++) {
            const int rloc = rq * 4 + rr;
            const int r    = rbase + rr;

            // W[r] -> registers from smem (conflict-free LDS.128)
            const float4* wrow = s_w + rloc * 320;
            float4 wa[5], wb[5];
            #pragma unroll
            for (int k = 0; k < 5; k++) {
                wa[k] = wrow[(2 * k)     * 32 + lane];
                wb[k] = wrow[(2 * k + 1) * 32 + lane];
            }

            float uhold[5];
            #pragma unroll
            for (int bb = 0; bb < 8; bb++) {
                float xc[8];
                #pragma unroll
                for (int c = 0; c < 8; c++)
                    xc[c] = __shfl_sync(0xffffffffu, xq[bb], rr * 8 + c);

                float u[5];
                #pragma unroll
                for (int k = 0; k < 5; k++) {
                    float t = wa[k].x * xc[0];
                    t = fmaf(wa[k].y, xc[1], t);
                    t = fmaf(wa[k].z, xc[2], t);
                    t = fmaf(wa[k].w, xc[3], t);
                    t = fmaf(wb[k].x, xc[4], t);
                    t = fmaf(wb[k].y, xc[5], t);
                    t = fmaf(wb[k].z, xc[6], t);
                    t = fmaf(wb[k].w, xc[7], t);
                    u[k] = t;
                }

                if (bb & 1) {
                    const int pp = bb >> 1;
                    __half2* up = g_U16 +
                        ((size_t)((b0 >> 1) + pp) * R_ + r) * JO_ + lane;
                    #pragma unroll
                    for (int k = 0; k < 5; k++) {
                        __half2 h = __floats2half2_rn(uhold[k], u[k]);
                        up[32 * k] = h;
                        sacc2[pp][k] = __hadd2(sacc2[pp][k], h);
                    }
                } else {
                    #pragma unroll
                    for (int k = 0; k < 5; k++) uhold[k] = u[k];
                }
            }
        }
    }

    // spread-address global atomics (40 per warp, 144-way contention; R8-proven)
    #pragma unroll
    for (int pp = 0; pp < 4; pp++)
        #pragma unroll
        for (int k = 0; k < 5; k++) {
            float2 s = __half22float2(sacc2[pp][k]);
            int jo = lane + 32 * k;
            atomicAdd(&g_S[0][(b0 + 2 * pp)     * JO_ + jo], s.x);
            atomicAdd(&g_S[0][(b0 + 2 * pp + 1) * JO_ + jo], s.y);
        }
}

// ---------------------------------------------------------------------------
// One routing iteration on a BATCH PAIR per warp: logits for b0 and b1 ride
// in the .x/.y halves of every half2 through the butterfly AND the softmax
// tail (HMAX2 tree, ex2.approx.f16x2, half2 z-tree, h2rcp). c*u accumulated
// with HFMA2 in half2, flushed to fp32 every 3 r (bounds fp16 accum noise).
// Lane l holds jo = l + 32k: lanes 0-15 j=2k, lanes 16-31 j=2k+1.
// Block-level smem reduction before global atomics (8 warps per block share
// the same pair p since 64%8==0): 8x fewer global atomic ops.
// (unchanged from R10/R11: 56us measured best)
__global__ void __launch_bounds__(256, 7) k_route(int vsel, int ssel) {
    __shared__ float s_red[2 * JO_];
    const int tid  = threadIdx.x;
    const int lane = tid & 31;
    const int unit = blockIdx.x * 8 + (tid >> 5);
    const int p    = unit >> 6;            // uniform per block
    const int sl   = unit & 63;            // 64 slices of 18 r
    const int b0   = 2 * p, b1 = b0 + 1;

    for (int i = tid; i < 2 * JO_; i += 256) s_red[i] = 0.f;
    __syncthreads();

    const float* __restrict__ V = vsel ? g_VSUM : g_V0;
    const float LOG2E = 1.4426950408889634f;

    __half2 v2[5];
    float sacc0[5] = {0.f, 0.f, 0.f, 0.f, 0.f};
    float sacc1[5] = {0.f, 0.f, 0.f, 0.f, 0.f};
    #pragma unroll
    for (int k = 0; k < 5; k++) {
        int jo = lane + 32 * k;
        v2[k] = __floats2half2_rn(V[b0 * JO_ + jo] * LOG2E,
                                  V[b1 * JO_ + jo] * LOG2E);
    }

    const __half2* __restrict__ up =
        g_U16 + ((size_t)p * R_ + (size_t)sl * 18) * JO_ + lane;

    for (int rq = 0; rq < 6; rq++) {
        __half2 hacc[5];
        #pragma unroll
        for (int k = 0; k < 5; k++) hacc[k] = __floats2half2_rn(0.f, 0.f);

        #pragma unroll
        for (int rr = 0; rr < 3; rr++) {
            __half2 u2[5], ap2[5];
            #pragma unroll
            for (int k = 0; k < 5; k++) u2[k] = up[32 * k];
            up += JO_;

            #pragma unroll
            for (int k = 0; k < 5; k++) ap2[k] = __hmul2(u2[k], v2[k]);

            // reduce over o (16 lanes per j-group), both batches per op
            #pragma unroll
            for (int d = 1; d < 16; d <<= 1) {
                #pragma unroll
                for (int k = 0; k < 5; k++)
                    ap2[k] = __hadd2(ap2[k],
                                     __shfl_xor_sync(0xffffffffu, ap2[k], d));
            }

            // max over all 10 j (both halves independently)
            __half2 m2 = __hmax2(ap2[0], ap2[1]);
            m2 = __hmax2(m2, ap2[2]);
            m2 = __hmax2(m2, ap2[3]);
            m2 = __hmax2(m2, ap2[4]);
            m2 = __hmax2(m2, __shfl_xor_sync(0xffffffffu, m2, 16));

            // e = exp2(a - m); z-tree; c = e / z; hacc += c * u
            #pragma unroll
            for (int k = 0; k < 5; k++) ap2[k] = h2exp2_(__hsub2(ap2[k], m2));
            __half2 z2 = __hadd2(ap2[0], ap2[1]);
            z2 = __hadd2(z2, ap2[2]);
            z2 = __hadd2(z2, ap2[3]);
            z2 = __hadd2(z2, ap2[4]);
            z2 = __hadd2(z2, __shfl_xor_sync(0xffffffffu, z2, 16));
            __half2 rz2 = h2rcp(z2);

            #pragma unroll
            for (int k = 0; k < 5; k++)
                hacc[k] = __hfma2(__hmul2(ap2[k], rz2), u2[k], hacc[k]);
        }

        // flush fp16 partials to fp32
        #pragma unroll
        for (int k = 0; k < 5; k++) {
            float2 t = __half22float2(hacc[k]);
            sacc0[k] += t.x;
            sacc1[k] += t.y;
        }
    }

    // block-level reduction: warps -> smem
    #pragma unroll
    for (int k = 0; k < 5; k++) {
        int jo = lane + 32 * k;
        atomicAdd(&s_red[jo],       sacc0[k]);
        atomicAdd(&s_red[JO_ + jo], sacc1[k]);
    }
    __syncthreads();

    float* __restrict__ Sout = g_S[ssel];
    for (int i = tid; i < 2 * JO_; i += 256)
        atomicAdd(&Sout[(size_t)b0 * JO_ + i], s_red[i]);
}

// ---------------------------------------------------------------------------
// v = squash(S * scale). mode 0: write g_V0. mode 1: g_VSUM = v + g_V0.
// mode 2: write dout (final output, [B,J,O,1] contiguous).
__global__ void k_squash(int ssel, float scale, int mode,
                         float* __restrict__ dout) {
    int i = blockIdx.x * blockDim.x + threadIdx.x;   // over B*J = 5120
    if (i >= B_ * J_) return;
    const float* s = g_S[ssel] + (size_t)i * O_;

    float sv[O_];
    float sq = 0.f;
    #pragma unroll
    for (int o = 0; o < O_; o++) {
        float t = s[o] * scale;
        sv[o] = t;
        sq += t * t;
    }
    float f = (sq / (1.0f + sq)) * rsqrtf(sq + 1e-8f);

    #pragma unroll
    for (int o = 0; o < O_; o++) {
        float vv = sv[o] * f;
        if (mode == 0)      g_V0[(size_t)i * O_ + o]   = vv;
        else if (mode == 1) g_VSUM[(size_t)i * O_ + o] = vv + g_V0[(size_t)i * O_ + o];
        else                dout[(size_t)i * O_ + o]   = vv;
    }
}

// ---------------------------------------------------------------------------
extern "C" void kernel_launch(void* const* d_in, const int* in_sizes, int n_in,
                              void* d_out, int out_size) {
    const float* x = (const float*)d_in[0];   // [512,1152,8]
    const float* W = (const float*)d_in[1];   // [1152,10,16,8]
    float* out = (float*)d_out;               // [512,10,16,1]
    (void)in_sizes; (void)n_in; (void)out_size;

    k_zero<<<240, 1024>>>();                          // zero S0,S1,S2
    k_uhat<<<1152, 256>>>(x, W);                      // u_hat(fp16) + sum_r -> S0
    k_squash<<<20, 256>>>(0, 1.0f / (float)J_, 0, nullptr);  // v0
    k_route<<<2048, 256>>>(0, 1);                     // iter 1 -> S1 (logits u.v0)
    k_squash<<<20, 256>>>(1, 1.0f, 1, nullptr);       // v1, VSUM = v0+v1
    k_route<<<2048, 256>>>(1, 2);                     // iter 2 -> S2 (logits u.(v0+v1))
    k_squash<<<20, 256>>>(2, 1.0f, 2, out);           // v2 -> output
}

// round 14
// speedup vs baseline: 1.2463x; 1.0010x over previous
#include <cuda_runtime.h>
#include <cuda_fp16.h>
#include <math.h>

#define B_  512
#define R_  1152
#define C_  8
#define J_  10
#define O_  16
#define JO_ 160

// Scratch (device globals: no allocations allowed in kernel_launch)
// u_hat stored fp16, packed across batch pairs: g_U16[p, r, jo] = (u[2p], u[2p+1])
__device__ __half2 g_U16[(size_t)(B_ / 2) * R_ * JO_];   // 188 MB
__device__ float   g_S[3][B_ * JO_];                     // s accumulators
__device__ float   g_V0[B_ * JO_];                       // v0
__device__ float   g_VSUM[B_ * JO_];                     // v0 + v1

__device__ __forceinline__ __half2 h2exp2_(__half2 x) {
    unsigned r, xi = *reinterpret_cast<unsigned*>(&x);
    asm("ex2.approx.f16x2 %0, %1;" : "=r"(r) : "r"(xi));
    return *reinterpret_cast<__half2*>(&r);
}

// ---------------------------------------------------------------------------
__global__ void k_zero() {
    int i = blockIdx.x * blockDim.x + threadIdx.x;
    if (i < 3 * B_ * JO_) ((float*)g_S)[i] = 0.0f;
}

// ---------------------------------------------------------------------------
// u_hat kernel — unchanged from R12 (proven ~73us).
__global__ void __launch_bounds__(256) k_uhat(const float* __restrict__ x,
                                              const float* __restrict__ W) {
    __shared__ float4 s_w[8 * 320];        // 8 r x 320 float4 = 40KB, swizzled
    const int tid  = threadIdx.x;
    const int lane = tid & 31;
    const int warp = tid >> 5;
    const int sl   = blockIdx.x % 144;     // 144 slices of 8 r
    const int bg   = blockIdx.x / 144;     // 8 groups of 64 b
    const int r0   = sl * 8;
    const int b0   = bg * 64 + warp * 8;   // this warp's 8 batches

    {
        const float4* Wg = (const float4*)(W + (size_t)r0 * 1280);
        for (int i = tid; i < 8 * 320; i += 256) {
            int r  = i / 320;
            int f  = i - r * 320;
            int jo = f >> 1, ch = f & 1;
            int k  = jo >> 5, l = jo & 31;
            s_w[r * 320 + (k * 2 + ch) * 32 + l] = Wg[r * 320 + f];
        }
    }
    __syncthreads();

    __half2 sacc2[4][5];
    #pragma unroll
    for (int pp = 0; pp < 4; pp++)
        #pragma unroll
        for (int k = 0; k < 5; k++) sacc2[pp][k] = __floats2half2_rn(0.f, 0.f);

    #pragma unroll
    for (int rq = 0; rq < 2; rq++) {
        const int rbase = r0 + rq * 4;

        float xq[8];
        #pragma unroll
        for (int bb = 0; bb < 8; bb++)
            xq[bb] = x[(size_t)(b0 + bb) * (R_ * C_) + (size_t)rbase * C_ + lane];

        #pragma unroll
        for (int rr = 0; rr < 4; rr++) {
            const int rloc = rq * 4 + rr;
            const int r    = rbase + rr;

            const float4* wrow = s_w + rloc * 320;
            float4 wa[5], wb[5];
            #pragma unroll
            for (int k = 0; k < 5; k++) {
                wa[k] = wrow[(2 * k)     * 32 + lane];
                wb[k] = wrow[(2 * k + 1) * 32 + lane];
            }

            float uhold[5];
            #pragma unroll
            for (int bb = 0; bb < 8; bb++) {
                float xc[8];
                #pragma unroll
                for (int c = 0; c < 8; c++)
                    xc[c] = __shfl_sync(0xffffffffu, xq[bb], rr * 8 + c);

                float u[5];
                #pragma unroll
                for (int k = 0; k < 5; k++) {
                    float t = wa[k].x * xc[0];
                    t = fmaf(wa[k].y, xc[1], t);
                    t = fmaf(wa[k].z, xc[2], t);
                    t = fmaf(wa[k].w, xc[3], t);
                    t = fmaf(wb[k].x, xc[4], t);
                    t = fmaf(wb[k].y, xc[5], t);
                    t = fmaf(wb[k].z, xc[6], t);
                    t = fmaf(wb[k].w, xc[7], t);
                    u[k] = t;
                }

                if (bb & 1) {
                    const int pp = bb >> 1;
                    __half2* up = g_U16 +
                        ((size_t)((b0 >> 1) + pp) * R_ + r) * JO_ + lane;
                    #pragma unroll
                    for (int k = 0; k < 5; k++) {
                        __half2 h = __floats2half2_rn(uhold[k], u[k]);
                        up[32 * k] = h;
                        sacc2[pp][k] = __hadd2(sacc2[pp][k], h);
                    }
                } else {
                    #pragma unroll
                    for (int k = 0; k < 5; k++) uhold[k] = u[k];
                }
            }
        }
    }

    #pragma unroll
    for (int pp = 0; pp < 4; pp++)
        #pragma unroll
        for (int k = 0; k < 5; k++) {
            float2 s = __half22float2(sacc2[pp][k]);
            int jo = lane + 32 * k;
            atomicAdd(&g_S[0][(b0 + 2 * pp)     * JO_ + jo], s.x);
            atomicAdd(&g_S[0][(b0 + 2 * pp + 1) * JO_ + jo], s.y);
        }
}

// ---------------------------------------------------------------------------
// Routing iteration v6.1 — in-thread o-reduction (MIO/LSU diet).
// Warp = (pair p, 12-r slice); lane = (rr = lane>>4 in {0,1}, j = lane&15,
// active j<10). Since U layout is jo = j*16+o, a lane loads all 16 o of its
// (r+rr, j) with 4 LDG.128 and does the dot u.v with 16 HFMA2 — NO shuffles
// for the o-reduction (was 20 SHFL/r). Softmax over j: one 4-step butterfly
// per quantity within each 16-lane half (idle lanes carry -60000 -> e=0).
// v in smem (block-uniform pair, bank-padded stride 20). Accumulation: fp16
// fine (4-r windows) -> fp16 coarse -> single fp32 smem epilogue per warp
// (plain STS; no atomics until one REDG pass per block).
// v6.1 FIX: idle lanes (j>=10) read v_s through a CLAMPED pointer — the R13
// crash was their unguarded vp4[q] read at j*20 running past the shared
// allocation. Clamped lanes read valid data, compute junk, stay masked.
__global__ void __launch_bounds__(256) k_route(int vsel, int ssel) {
    __shared__ float   s_priv[16 * 320];   // [region = w*2+rr][b*160 + o*10+j]
    __shared__ __half2 v_s[10 * 20];       // padded: v_s[j*20+o]
    const int tid  = threadIdx.x;
    const int lane = tid & 31;
    const int w    = tid >> 5;
    const int p    = blockIdx.x / 12;      // 256 pairs x 12 blocks
    const int g    = blockIdx.x - p * 12;
    const int slice = g * 8 + w;           // 0..95, 12 r each
    const int r0   = slice * 12;
    const int rr   = lane >> 4;
    const int j    = lane & 15;
    const bool act = (j < 10);
    const int jc   = act ? j : 0;          // clamped for all unguarded reads
    const int b0   = 2 * p;

    const float* __restrict__ V = vsel ? g_VSUM : g_V0;
    const float LOG2E = 1.4426950408889634f;

    // stage v (block-uniform): v_s[j*20+o] = (V[b0,j,o], V[b1,j,o]) * log2e
    for (int t = tid; t < 160; t += 256) {
        int jj = t >> 4, oo = t & 15;
        v_s[jj * 20 + oo] = __floats2half2_rn(V[b0 * JO_ + t] * LOG2E,
                                              V[(b0 + 1) * JO_ + t] * LOG2E);
    }
    __syncthreads();

    const __half2 HZERO = __floats2half2_rn(0.f, 0.f);
    const __half2 NEG   = __floats2half2_rn(-60000.f, -60000.f);
    __half2 fine[16], coarse[16];
    #pragma unroll
    for (int o = 0; o < 16; o++) { fine[o] = HZERO; coarse[o] = HZERO; }

    // u pointer also clamped (loads are guarded, but keep the address valid)
    const __half2* __restrict__ ubase =
        g_U16 + ((size_t)p * R_ + r0 + rr) * JO_ + jc * 16;
    const uint4* vp4 = (const uint4*)(v_s + jc * 20);  // 80B-aligned, in-bounds

    #pragma unroll 2
    for (int step = 0; step < 6; step++) {
        // load u[r, j, 0..15] (b-paired half2) — 4x LDG.128, active lanes only
        __half2 u2[16];
        if (act) {
            const uint4* up4 =
                (const uint4*)(ubase + (size_t)(2 * step) * JO_);
            #pragma unroll
            for (int q = 0; q < 4; q++) {
                uint4 t = up4[q];
                u2[q * 4 + 0] = *(__half2*)&t.x;
                u2[q * 4 + 1] = *(__half2*)&t.y;
                u2[q * 4 + 2] = *(__half2*)&t.z;
                u2[q * 4 + 3] = *(__half2*)&t.w;
            }
        } else {
            #pragma unroll
            for (int o = 0; o < 16; o++) u2[o] = HZERO;
        }

        // in-thread dot over o (two chains for ILP), both batches per HFMA2
        __half2 aA = HZERO, aB = HZERO;
        #pragma unroll
        for (int q = 0; q < 4; q++) {
            uint4 vq = vp4[q];
            aA = __hfma2(u2[q * 4 + 0], *(__half2*)&vq.x, aA);
            aB = __hfma2(u2[q * 4 + 1], *(__half2*)&vq.y, aB);
            aA = __hfma2(u2[q * 4 + 2], *(__half2*)&vq.z, aA);
            aB = __hfma2(u2[q * 4 + 3], *(__half2*)&vq.w, aB);
        }
        __half2 a2 = __hadd2(aA, aB);
        if (!act) a2 = NEG;                 // idle lanes neutral

        // softmax over j within each 16-lane half (4+4 SHFL total)
        __half2 m2 = a2;
        #pragma unroll
        for (int d = 1; d < 16; d <<= 1)
            m2 = __hmax2(m2, __shfl_xor_sync(0xffffffffu, m2, d));
        __half2 e2 = h2exp2_(__hsub2(a2, m2));
        __half2 z2 = e2;
        #pragma unroll
        for (int d = 1; d < 16; d <<= 1)
            z2 = __hadd2(z2, __shfl_xor_sync(0xffffffffu, z2, d));
        __half2 c2 = __hmul2(e2, h2rcp(z2));

        // accumulate c*u (idle lanes accumulate zeros — never stored anyway)
        #pragma unroll
        for (int o = 0; o < 16; o++)
            fine[o] = __hfma2(c2, u2[o], fine[o]);

        if (step & 1) {                     // fold 4-r window into coarse
            #pragma unroll
            for (int o = 0; o < 16; o++) {
                coarse[o] = __hadd2(coarse[o], fine[o]);
                fine[o] = HZERO;
            }
        }
    }

    // per-warp epilogue: coarse -> fp32 private smem region (no atomics)
    if (act) {
        const int reg = (w * 2 + rr) * 320;
        #pragma unroll
        for (int o = 0; o < 16; o++) {
            float2 f = __half22float2(coarse[o]);
            s_priv[reg +       o * 10 + j] = f.x;
            s_priv[reg + 160 + o * 10 + j] = f.y;
        }
    }
    __syncthreads();

    // block tree: sum 16 regions in fp32, one atomic pass to g_S
    float* __restrict__ Sout = g_S[ssel];
    for (int t = tid; t < 320; t += 256) {
        float acc = s_priv[t];
        #pragma unroll
        for (int k = 1; k < 16; k++) acc += s_priv[k * 320 + t];
        int bb  = t / 160;
        int rem = t - bb * 160;
        int o   = rem / 10;
        int jj  = rem - o * 10;
        atomicAdd(&Sout[(size_t)(b0 + bb) * JO_ + jj * 16 + o], acc);
    }
}

// ---------------------------------------------------------------------------
// v = squash(S * scale). mode 0: write g_V0. mode 1: g_VSUM = v + g_V0.
// mode 2: write dout (final output, [B,J,O,1] contiguous).
__global__ void k_squash(int ssel, float scale, int mode,
                         float* __restrict__ dout) {
    int i = blockIdx.x * blockDim.x + threadIdx.x;   // over B*J = 5120
    if (i >= B_ * J_) return;
    const float* s = g_S[ssel] + (size_t)i * O_;

    float sv[O_];
    float sq = 0.f;
    #pragma unroll
    for (int o = 0; o < O_; o++) {
        float t = s[o] * scale;
        sv[o] = t;
        sq += t * t;
    }
    float f = (sq / (1.0f + sq)) * rsqrtf(sq + 1e-8f);

    #pragma unroll
    for (int o = 0; o < O_; o++) {
        float vv = sv[o] * f;
        if (mode == 0)      g_V0[(size_t)i * O_ + o]   = vv;
        else if (mode == 1) g_VSUM[(size_t)i * O_ + o] = vv + g_V0[(size_t)i * O_ + o];
        else                dout[(size_t)i * O_ + o]   = vv;
    }
}

// ---------------------------------------------------------------------------
extern "C" void kernel_launch(void* const* d_in, const int* in_sizes, int n_in,
                              void* d_out, int out_size) {
    const float* x = (const float*)d_in[0];   // [512,1152,8]
    const float* W = (const float*)d_in[1];   // [1152,10,16,8]
    float* out = (float*)d_out;               // [512,10,16,1]
    (void)in_sizes; (void)n_in; (void)out_size;

    k_zero<<<240, 1024>>>();                          // zero S0,S1,S2
    k_uhat<<<1152, 256>>>(x, W);                      // u_hat(fp16) + sum_r -> S0
    k_squash<<<20, 256>>>(0, 1.0f / (float)J_, 0, nullptr);  // v0
    k_route<<<3072, 256>>>(0, 1);                     // iter 1 -> S1 (logits u.v0)
    k_squash<<<20, 256>>>(1, 1.0f, 1, nullptr);       // v1, VSUM = v0+v1
    k_route<<<3072, 256>>>(1, 2);                     // iter 2 -> S2 (logits u.(v0+v1))
    k_squash<<<20, 256>>>(2, 1.0f, 2, out);           // v2 -> output
}